// round 13
// baseline (speedup 1.0000x reference)
#include <cuda_runtime.h>

typedef unsigned long long u64;
typedef unsigned int u32;

#define NEG_INF_F (-3.4028234663852886e38f)
#define CAP   4096
#define HCAP  4096
#define NBINS 1024
#define BSHIFT 14
#define SSZ   512
#define TOPN  64
#define SPLIT 4
#define MAXB  256
#define NT1   1024
#define NT4   512
#define LOCAL (CAP/NT4)
#define PRNG_SCHEME 2   // 2 = partitionable (xor-fold, modern JAX default), 1 = legacy split-half

__device__ float g_smax[MAXB*SPLIT], g_ssum[MAXB*SPLIT], g_sssq[MAXB*SPLIT], g_sexp[MAXB*SPLIT];
__device__ u64 g_cand[(size_t)MAXB*CAP];
__device__ int g_cnt[MAXB];

__device__ __forceinline__ u32 fkey(float f){
  u32 u = __float_as_uint(f);
  return (u & 0x80000000u) ? ~u : (u | 0x80000000u);
}
__device__ __forceinline__ float fdec(u32 s){
  u32 u = (s & 0x80000000u) ? (s ^ 0x80000000u) : ~s;
  return __uint_as_float(u);
}
__device__ __forceinline__ void tfb(u32& x0, u32& x1, int r0, int r1, int r2, int r3){
  x0 += x1; x1 = __funnelshift_l(x1, x1, r0); x1 ^= x0;
  x0 += x1; x1 = __funnelshift_l(x1, x1, r1); x1 ^= x0;
  x0 += x1; x1 = __funnelshift_l(x1, x1, r2); x1 ^= x0;
  x0 += x1; x1 = __funnelshift_l(x1, x1, r3); x1 ^= x0;
}
__device__ __forceinline__ void threefry42(u32 c0, u32 c1, u32& o0, u32& o1){
  const u32 k0 = 0u, k1 = 42u, k2 = 0x1BD11BDAu ^ k0 ^ k1;
  u32 x0 = c0 + k0, x1 = c1 + k1;
  tfb(x0,x1,13,15,26,6);  x0 += k1; x1 += k2 + 1u;
  tfb(x0,x1,17,29,16,24); x0 += k2; x1 += k0 + 2u;
  tfb(x0,x1,13,15,26,6);  x0 += k0; x1 += k1 + 3u;
  tfb(x0,x1,17,29,16,24); x0 += k1; x1 += k2 + 4u;
  tfb(x0,x1,13,15,26,6);  x0 += k2; x1 += k0 + 5u;
  o0 = x0; o1 = x1;
}
__device__ __forceinline__ float gumbel_at(u64 j, u64 half){
  u32 o0, o1, bits;
#if PRNG_SCHEME == 1
  if (j < half){ threefry42((u32)j, (u32)(j + half), o0, o1); bits = o0; }
  else         { threefry42((u32)(j - half), (u32)j, o0, o1); bits = o1; }
#else
  threefry42((u32)(j >> 32), (u32)j, o0, o1); bits = o0 ^ o1;
#endif
  float u = __uint_as_float((bits >> 9) | 0x3f800000u) - 1.0f;
  float v = fmaxf(1e-10f, u + 1e-10f);
  return -logf(-logf(v));
}

// ---------------- K1: per-slice max/sum/ssq (one DRAM pass) ----------------
__global__ void __launch_bounds__(NT1, 1)
k1_stats(const float* __restrict__ logits, int V, int Vs)
{
  const int row = blockIdx.x / SPLIT, sl = blockIdx.x % SPLIT;
  const int tid = threadIdx.x, lane = tid & 31, wid = tid >> 5;
  if (sl == 0 && tid == 0) g_cnt[row] = 0;
  const float* lrow = logits + (size_t)row * V;
  int e0 = sl * Vs; if (e0 > V) e0 = V;
  int e1 = e0 + Vs; if (e1 > V) e1 = V;
  const int f0 = e0 >> 2, f1 = e1 >> 2;
  const float4* l4 = (const float4*)lrow;
  __shared__ float r0[32], r1[32], r2[32];
  float m = __int_as_float(0xff800000), sum = 0.f, ssq = 0.f;
  for (int i = f0 + tid; i < f1; i += NT1){
    float4 v = l4[i];
    m = fmaxf(m, fmaxf(fmaxf(v.x, v.y), fmaxf(v.z, v.w)));
    sum += (v.x + v.y) + (v.z + v.w);
    ssq += v.x*v.x + v.y*v.y + v.z*v.z + v.w*v.w;
  }
  for (int i = (f1 << 2) + tid; i < e1; i += NT1){
    float x = lrow[i]; m = fmaxf(m, x); sum += x; ssq += x * x;
  }
  #pragma unroll
  for (int o = 16; o; o >>= 1){
    m   = fmaxf(m, __shfl_down_sync(~0u, m, o));
    sum += __shfl_down_sync(~0u, sum, o);
    ssq += __shfl_down_sync(~0u, ssq, o);
  }
  if (lane == 0){ r0[wid] = m; r1[wid] = sum; r2[wid] = ssq; }
  __syncthreads();
  if (wid == 0){
    m = r0[lane]; sum = r1[lane]; ssq = r2[lane];
    #pragma unroll
    for (int o = 16; o; o >>= 1){
      m   = fmaxf(m, __shfl_down_sync(~0u, m, o));
      sum += __shfl_down_sync(~0u, sum, o);
      ssq += __shfl_down_sync(~0u, ssq, o);
    }
    if (lane == 0){
      g_smax[row*SPLIT+sl] = m; g_ssum[row*SPLIT+sl] = sum; g_sssq[row*SPLIT+sl] = ssq;
    }
  }
}

// ---------------- K3: sumexp + candidate gather (L2 pass) ----------------
__global__ void __launch_bounds__(NT1, 1)
k3_gather(const float* __restrict__ logits, int V, int Vs)
{
  const int row = blockIdx.x / SPLIT, sl = blockIdx.x % SPLIT;
  const int tid = threadIdx.x, lane = tid & 31, wid = tid >> 5;
  const float* lrow = logits + (size_t)row * V;
  float m = __int_as_float(0xff800000), sum = 0.f, ssq = 0.f;
  #pragma unroll
  for (int s = 0; s < SPLIT; s++){
    m = fmaxf(m, g_smax[row*SPLIT+s]);
    sum += g_ssum[row*SPLIT+s]; ssq += g_sssq[row*SPLIT+s];
  }
  float mu = sum / (float)V;
  float sig = sqrtf(fmaxf(ssq / (float)V - mu * mu, 0.f));
  const float T = fminf(mu + 2.0f * sig, m);
  const float bm = g_smax[row*SPLIT+sl];
  int e0 = sl * Vs; if (e0 > V) e0 = V;
  int e1 = e0 + Vs; if (e1 > V) e1 = V;
  const int f0 = e0 >> 2, f1 = e1 >> 2;
  const float4* l4 = (const float4*)lrow;
  __shared__ float r0[32];
  float se = 0.f;
  const int iters = (f1 - f0 + NT1 - 1) / NT1;
  for (int t = 0; t < iters; t++){
    int i = f0 + t * NT1 + tid;
    bool in = (i < f1);
    float4 v = in ? l4[i] : make_float4(NEG_INF_F, NEG_INF_F, NEG_INF_F, NEG_INF_F);
    if (in) se += __expf(v.x-bm) + __expf(v.y-bm) + __expf(v.z-bm) + __expf(v.w-bm);
    float xs[4] = {v.x, v.y, v.z, v.w};
    u32 mk[4]; int pc[4];
    #pragma unroll
    for (int c2 = 0; c2 < 4; c2++){
      mk[c2] = __ballot_sync(~0u, in && (xs[c2] >= T));
      pc[c2] = __popc(mk[c2]);
    }
    int total = pc[0] + pc[1] + pc[2] + pc[3];
    if (total){
      int base = 0;
      if (lane == 0) base = atomicAdd(&g_cnt[row], total);
      base = __shfl_sync(~0u, base, 0);
      int run = 0, bi = i << 2;
      u32 lt = (1u << lane) - 1u;
      #pragma unroll
      for (int c2 = 0; c2 < 4; c2++){
        if (mk[c2] & (1u << lane)){
          int p = base + run + __popc(mk[c2] & lt);
          if (p < CAP) g_cand[(size_t)row*CAP + p] = ((u64)fkey(xs[c2]) << 32) | (u32)~(u32)(bi + c2);
        }
        run += pc[c2];
      }
    }
  }
  for (int i = (f1 << 2) + tid; i < e1; i += NT1){
    float x = lrow[i];
    se += __expf(x - bm);
    if (x >= T){
      int p = atomicAdd(&g_cnt[row], 1);
      if (p < CAP) g_cand[(size_t)row*CAP + p] = ((u64)fkey(x) << 32) | (u32)~(u32)i;
    }
  }
  #pragma unroll
  for (int o = 16; o; o >>= 1) se += __shfl_down_sync(~0u, se, o);
  if (lane == 0) r0[wid] = se;
  __syncthreads();
  if (wid == 0){
    se = r0[lane];
    #pragma unroll
    for (int o = 16; o; o >>= 1) se += __shfl_down_sync(~0u, se, o);
    if (lane == 0) g_sexp[row*SPLIT+sl] = se;
  }
}

// ---------------- K4: selection + outputs (2 CTAs per row) ----------------
__global__ void __launch_bounds__(NT4, 2)
sampler_kernel(const float* __restrict__ logits, const float* __restrict__ temperature,
               const float* __restrict__ presence, const float* __restrict__ frequency,
               const float* __restrict__ repetition, const float* __restrict__ top_p,
               const int* __restrict__ prompt_ids, const int* __restrict__ out_tok,
               const int* __restrict__ out_lens, const int* __restrict__ stop_ids,
               const int* __restrict__ min_toks, const int* __restrict__ top_k,
               float* __restrict__ out, int B, int V, int P, int O, int S, int MN)
{
  extern __shared__ unsigned char smraw[];
  u64* cbuf = (u64*)smraw;              // CAP u64 (fallback gather + survivor buffer)
  u32* hkey = (u32*)(cbuf + CAP);       // HCAP
  u32* hval = hkey + HCAP;              // HCAP
  u32* hist = hval + HCAP;              // NBINS
  __shared__ u32 red32[16];
  __shared__ int sh_cnt, sh_b, sh_c;
  __shared__ u32 sh_km;
  __shared__ float e_val[TOPN], e_gum[TOPN], e_exp[TOPN];
  __shared__ u32 e_idx[TOPN];

  const int row = blockIdx.x >> 1;
  const bool rawp = !(blockIdx.x & 1);
  const int tid = threadIdx.x, lane = tid & 31, wid = tid >> 5;
  const float* lrow = logits + (size_t)row * V;

  // row stats from partials
  float m = __int_as_float(0xff800000), sum = 0.f, ssq = 0.f;
  float ms[SPLIT];
  #pragma unroll
  for (int s = 0; s < SPLIT; s++){
    ms[s] = g_smax[row*SPLIT+s];
    m = fmaxf(m, ms[s]);
    sum += g_ssum[row*SPLIT+s]; ssq += g_sssq[row*SPLIT+s];
  }
  float Z = 0.f;
  #pragma unroll
  for (int s = 0; s < SPLIT; s++) Z += g_sexp[row*SPLIT+s] * __expf(ms[s] - m);
  const float logZ = logf(Z);
  const float mu = sum / (float)V;
  const float sig = sqrtf(fmaxf(ssq / (float)V - mu * mu, 0.f));
  int minc = P + O + S + TOPN; if (minc > V) minc = V;
  int c = g_cnt[row];

  u64 rk[LOCAL];
  if (c >= minc && c <= CAP){
    #pragma unroll
    for (int q = 0; q < LOCAL; q++){
      int p = q * NT4 + tid;
      rk[q] = (p < c) ? g_cand[(size_t)row*CAP + p] : 0ULL;
    }
  } else {
    // cold fallback: re-gather full row with bisection on T
    float lo = mu - 4.0f * sig - 1e-6f, hi = m;
    float T = fminf(mu + 2.0f * sig, hi);
    for (int it = 0; it < 40; it++){
      if (tid == 0) sh_cnt = 0;
      __syncthreads();
      int cc = 0;
      for (int i = tid; i < V; i += NT4) if (lrow[i] >= T) cc++;
      #pragma unroll
      for (int o = 16; o; o >>= 1) cc += __shfl_down_sync(~0u, cc, o);
      if (lane == 0 && cc) atomicAdd(&sh_cnt, cc);
      __syncthreads();
      int tot = sh_cnt;
      if (tot >= minc && tot <= CAP) break;
      if (tot > CAP) lo = T; else hi = T;
      T = 0.5f * (lo + hi);
      __syncthreads();
    }
    if (tid == 0) sh_cnt = 0;
    __syncthreads();
    for (int i = tid; i < V + (NT4 - V % NT4) % NT4; i += NT4){
      bool pred = (i < V) && (lrow[i] >= T);
      float x = pred ? lrow[i] : 0.f;
      u32 mk = __ballot_sync(~0u, pred);
      if (mk){
        int leader = __ffs(mk) - 1, pos = 0;
        if (lane == leader) pos = atomicAdd(&sh_cnt, __popc(mk));
        pos = __shfl_sync(~0u, pos, leader);
        if (pred){
          int p = pos + __popc(mk & ((1u << lane) - 1u));
          if (p < CAP) cbuf[p] = ((u64)fkey(x) << 32) | (u32)~(u32)i;
        }
      }
    }
    __syncthreads();
    c = sh_cnt; if (c > CAP) c = CAP;
    #pragma unroll
    for (int q = 0; q < LOCAL; q++){
      int p = q * NT4 + tid;
      rk[q] = (p < c) ? cbuf[p] : 0ULL;
    }
    __syncthreads();
  }
  if (c < 1) c = 1;

  // histogram top-select: >= n_need survivors (<= SSZ) into cbuf
  auto select_top = [&](int n_need)->int{
    for (int i = tid; i < NBINS; i += NT4) hist[i] = 0;
    u32 km = 0;
    #pragma unroll
    for (int q = 0; q < LOCAL; q++) if (rk[q]){ u32 h = (u32)(rk[q] >> 32); if (h > km) km = h; }
    #pragma unroll
    for (int o = 16; o; o >>= 1){ u32 t = __shfl_down_sync(~0u, km, o); if (t > km) km = t; }
    if (lane == 0) red32[wid] = km;
    __syncthreads();
    if (wid == 0){
      km = (lane < NT4/32) ? red32[lane] : 0u;
      #pragma unroll
      for (int o = 16; o; o >>= 1){ u32 t = __shfl_down_sync(~0u, km, o); if (t > km) km = t; }
      if (lane == 0) sh_km = km;
    }
    __syncthreads();
    km = sh_km;
    #pragma unroll
    for (int q = 0; q < LOCAL; q++) if (rk[q]){
      u32 d = km - (u32)(rk[q] >> 32);
      int b = (int)(d >> BSHIFT); if (b > NBINS-1) b = NBINS-1;
      atomicAdd(&hist[b], 1u);
    }
    __syncthreads();
    if (wid == 0){
      int cum = 0, bstar = NBINS - 1, cumv = 0, found = 0;
      for (int ch = 0; ch < NBINS/32; ch++){
        int v = (int)hist[ch*32 + lane];
        int sc2 = v;
        #pragma unroll
        for (int o = 1; o < 32; o <<= 1){ int t = __shfl_up_sync(~0u, sc2, o); if (lane >= o) sc2 += t; }
        int tot = __shfl_sync(~0u, sc2, 31);
        if (!found){
          u32 ok = __ballot_sync(~0u, cum + sc2 >= n_need);
          if (ok){
            int l = __ffs(ok) - 1;
            bstar = ch*32 + l; cumv = cum + __shfl_sync(~0u, sc2, l); found = 1;
          }
        }
        cum += tot;
      }
      if (!found){ bstar = NBINS - 1; cumv = cum; }
      if (lane == 0){ sh_b = bstar; sh_c = cumv; }
    }
    __syncthreads();
    int bstar = sh_b, cnt = sh_c;
    u32 thr = 0; bool useThr = false;
    if (cnt > SSZ){
      u32 blo = 1u, bhi = 0xFFFFFFFFu, best = 1u;
      for (int it = 0; it < 34; it++){
        u32 mid = blo + ((bhi - blo) >> 1);
        __syncthreads();
        if (tid == 0) sh_cnt = 0;
        __syncthreads();
        int cc = 0;
        #pragma unroll
        for (int q = 0; q < LOCAL; q++) if (rk[q] && (u32)(rk[q] >> 32) >= mid) cc++;
        #pragma unroll
        for (int o = 16; o; o >>= 1) cc += __shfl_down_sync(~0u, cc, o);
        if (lane == 0 && cc) atomicAdd(&sh_cnt, cc);
        __syncthreads();
        int tot = sh_cnt;
        if (tot >= n_need && tot <= SSZ){ best = mid; break; }
        if (tot > SSZ) blo = mid + 1; else bhi = mid - 1;
      }
      thr = best; useThr = true;
    }
    __syncthreads();
    if (tid == 0) sh_cnt = 0;
    __syncthreads();
    #pragma unroll
    for (int q = 0; q < LOCAL; q++){
      bool pred;
      if (useThr) pred = rk[q] && ((u32)(rk[q] >> 32) >= thr);
      else {
        int b = NBINS;
        if (rk[q]){ u32 d = km - (u32)(rk[q] >> 32); b = (int)(d >> BSHIFT); if (b > NBINS-1) b = NBINS-1; }
        pred = rk[q] && (b <= bstar);
      }
      u32 mk = __ballot_sync(~0u, pred);
      if (mk){
        int leader = __ffs(mk) - 1, pos = 0;
        if (lane == leader) pos = atomicAdd(&sh_cnt, __popc(mk));
        pos = __shfl_sync(~0u, pos, leader);
        if (pred){
          int p = pos + __popc(mk & ((1u << lane) - 1u));
          if (p < SSZ) cbuf[p] = rk[q];
        }
      }
    }
    __syncthreads();
    int sc2 = sh_cnt; if (sc2 > SSZ) sc2 = SSZ;
    return sc2;
  };

  auto sortbuf = [&](int SZ){
    for (int kk = 2; kk <= SZ; kk <<= 1)
      for (int j = kk >> 1; j > 0; j >>= 1){
        __syncthreads();
        if (tid < SZ){
          int l = tid ^ j;
          if (l > tid){
            u64 a = cbuf[tid], b2 = cbuf[l];
            bool asc = ((tid & kk) == 0);
            if (asc ? (a > b2) : (a < b2)){ cbuf[tid] = b2; cbuf[l] = a; }
          }
        }
      }
    __syncthreads();
  };

  if (rawp){
    // ---- even CTA: top-MN raw logprobs + indices ----
    int need = (MN < c) ? MN : c;
    if (need < 1) need = 1;
    int sc = select_top(need);
    int SZ = 32; while (SZ < sc) SZ <<= 1;
    for (int i = sc + tid; i < SZ; i += NT4) cbuf[i] = 0ULL;
    __syncthreads();
    sortbuf(SZ);
    int mrounds = (MN < c) ? MN : c;
    if (tid < MN){
      if (tid < mrounds){
        u64 w = cbuf[SZ - 1 - tid];
        out[(size_t)B + (size_t)row*MN + tid] = (fdec((u32)(w >> 32)) - m) - logZ;
        out[(size_t)B + (size_t)B*MN + (size_t)row*MN + tid] = (float)(~(u32)w);
      } else {
        out[(size_t)B + (size_t)row*MN + tid] = 0.f;
        out[(size_t)B + (size_t)B*MN + (size_t)row*MN + tid] = 0.f;
      }
    }
  } else {
    // ---- odd CTA: penalties + top-k/top-p/gumbel sampling ----
    for (int i = tid; i < HCAP; i += NT4){ hkey[i] = 0xFFFFFFFFu; hval[i] = 0u; }
    __syncthreads();
    const int olen = out_lens[row];
    const bool penal = olen < min_toks[row];
    auto insert = [&](int id, u32 orb, u32 add){
      u32 uid = (u32)id, h = ((uid * 2654435761u) >> 16) & (HCAP - 1);
      for (;;){
        u32 k = hkey[h];
        if (k == uid) break;
        if (k == 0xFFFFFFFFu){
          u32 old = atomicCAS(&hkey[h], 0xFFFFFFFFu, uid);
          if (old == 0xFFFFFFFFu || old == uid) break;
        }
        h = (h + 1) & (HCAP - 1);
      }
      if (orb) atomicOr(&hval[h], orb);
      if (add) atomicAdd(&hval[h], add);
    };
    for (int i = tid; i < P; i += NT4) insert(prompt_ids[(size_t)row*P + i], 1u<<16, 0u);
    for (int i = tid; i < O; i += NT4) if (i < olen) insert(out_tok[(size_t)row*O + i], 0u, 1u);
    if (penal) for (int i = tid; i < S; i += NT4) insert(stop_ids[(size_t)row*S + i], 1u<<17, 0u);
    __syncthreads();

    const float rep = repetition[row], fr = frequency[row], pr = presence[row];
    const float tp = temperature[row], td = (tp < 1e-5f) ? 1.f : tp;
    #pragma unroll
    for (int q = 0; q < LOCAL; q++){
      u64 k = rk[q];
      if (k != 0ULL){
        u32 idx = ~(u32)k;
        float x = fdec((u32)(k >> 32));
        u32 h = ((idx * 2654435761u) >> 16) & (HCAP - 1), info = 0;
        for (;;){
          u32 kk = hkey[h];
          if (kk == idx){ info = hval[h]; break; }
          if (kk == 0xFFFFFFFFu) break;
          h = (h + 1) & (HCAP - 1);
        }
        int cv = (int)(info & 0xFFFFu);
        if (info & (1u<<17)) x = NEG_INF_F;
        if ((info & (1u<<16)) || cv > 0) x = (x > 0.f) ? (x / rep) : (x * rep);
        x = x - fr * (float)cv;
        if (cv > 0) x = x - pr;
        x = x / td;
        rk[q] = ((u64)fkey(x) << 32) | (u32)~idx;
      }
    }

    const int trounds = (TOPN < c) ? TOPN : c;
    int sc = select_top(trounds);
    int SZ = 32; while (SZ < sc) SZ <<= 1;
    for (int i = sc + tid; i < SZ; i += NT4) cbuf[i] = 0ULL;
    __syncthreads();
    sortbuf(SZ);

    const u64 half = ((u64)B * (u64)V) >> 1;
    if (tid < trounds){
      u64 w = cbuf[SZ - 1 - tid];
      float x = fdec((u32)(w >> 32));
      u32 ix = ~(u32)w;
      e_val[tid] = x; e_idx[tid] = ix;
      e_gum[tid] = gumbel_at((u64)row * (u64)V + ix, half);
    }
    __syncthreads();
    if (tid < trounds) e_exp[tid] = expf(e_val[tid] - e_val[0]);
    __syncthreads();
    if (tid == 0){
      int k = top_k[row];
      if (k < 1) k = 1;
      if (k > trounds) k = trounds;
      float kth = e_val[k - 1];
      float Ssum = 0.f; int k2 = 0;
      for (int j = 0; j < trounds; j++){
        if (e_val[j] >= kth){ Ssum += e_exp[j]; k2 = j + 1; } else break;
      }
      const float thr = top_p[row] * Ssum;
      float pref = 0.f, best = __int_as_float(0xff800000);
      u32 besti = e_idx[0];
      for (int j = 0; j < k2; j++){
        bool keep = (j == 0) || (pref < thr);
        pref += e_exp[j];
        if (keep){
          float sc2 = e_val[j] + e_gum[j];
          if (sc2 > best){ best = sc2; besti = e_idx[j]; }
        }
      }
      out[row] = (float)((tp < 1e-5f) ? e_idx[0] : besti);
    }
  }
}

extern "C" void kernel_launch(void* const* d_in, const int* in_sizes, int n_in,
                              void* d_out, int out_size)
{
  const float* logits = (const float*)d_in[0];
  int B = in_sizes[1];
  int V = in_sizes[0] / B;
  int P = in_sizes[6] / B;
  int O = in_sizes[7] / B;
  int S = in_sizes[9] / B;
  int MN = (out_size / B - 1) / 2;
  if (MN < 0) MN = 0;
  int Vs = (((V + SPLIT - 1) / SPLIT) + 31) & ~31;

  k1_stats<<<B * SPLIT, NT1>>>(logits, V, Vs);
  k3_gather<<<B * SPLIT, NT1>>>(logits, V, Vs);

  size_t sh = (size_t)CAP * sizeof(u64) + (size_t)HCAP * 2 * sizeof(u32)
            + (size_t)NBINS * sizeof(u32);
  cudaFuncSetAttribute(sampler_kernel, cudaFuncAttributeMaxDynamicSharedMemorySize, (int)sh);
  sampler_kernel<<<2 * B, NT4, sh>>>(logits,
      (const float*)d_in[1], (const float*)d_in[2], (const float*)d_in[3],
      (const float*)d_in[4], (const float*)d_in[5],
      (const int*)d_in[6], (const int*)d_in[7], (const int*)d_in[8],
      (const int*)d_in[9], (const int*)d_in[10], (const int*)d_in[11],
      (float*)d_out, B, V, P, O, S, MN);
}

// round 14
// speedup vs baseline: 2.2439x; 2.2439x over previous
#include <cuda_runtime.h>

typedef unsigned long long u64;
typedef unsigned int u32;

#define NEG_INF_F (-3.4028234663852886e38f)
#define CCAP  2048      // KC smem candidate buffer (fallback path may use all)
#define GCAP  1024      // per-row global gather capacity (hot path ~173)
#define HCAP  4096
#define TOPN  64
#define SPLITB 16
#define MAXB  256
#define NTA   256
#define NTB   256
#define NTC   512
#define PRNG_SCHEME 2   // 2 = partitionable (validated PASS), 1 = legacy split-half

__device__ float g_T[MAXB], g_M[MAXB];
__device__ float g_sexp[MAXB*SPLITB];
__device__ u64 g_cand[(size_t)MAXB*GCAP];
__device__ int g_cnt[MAXB];

__device__ __forceinline__ u32 fkey(float f){
  u32 u = __float_as_uint(f);
  return (u & 0x80000000u) ? ~u : (u | 0x80000000u);
}
__device__ __forceinline__ float fdec(u32 s){
  u32 u = (s & 0x80000000u) ? (s ^ 0x80000000u) : ~s;
  return __uint_as_float(u);
}
__device__ __forceinline__ void tfb(u32& x0, u32& x1, int r0, int r1, int r2, int r3){
  x0 += x1; x1 = __funnelshift_l(x1, x1, r0); x1 ^= x0;
  x0 += x1; x1 = __funnelshift_l(x1, x1, r1); x1 ^= x0;
  x0 += x1; x1 = __funnelshift_l(x1, x1, r2); x1 ^= x0;
  x0 += x1; x1 = __funnelshift_l(x1, x1, r3); x1 ^= x0;
}
__device__ __forceinline__ void threefry42(u32 c0, u32 c1, u32& o0, u32& o1){
  const u32 k0 = 0u, k1 = 42u, k2 = 0x1BD11BDAu ^ k0 ^ k1;
  u32 x0 = c0 + k0, x1 = c1 + k1;
  tfb(x0,x1,13,15,26,6);  x0 += k1; x1 += k2 + 1u;
  tfb(x0,x1,17,29,16,24); x0 += k2; x1 += k0 + 2u;
  tfb(x0,x1,13,15,26,6);  x0 += k0; x1 += k1 + 3u;
  tfb(x0,x1,17,29,16,24); x0 += k1; x1 += k2 + 4u;
  tfb(x0,x1,13,15,26,6);  x0 += k2; x1 += k0 + 5u;
  o0 = x0; o1 = x1;
}
__device__ __forceinline__ float gumbel_at(u64 j, u64 half){
  u32 o0, o1, bits;
#if PRNG_SCHEME == 1
  if (j < half){ threefry42((u32)j, (u32)(j + half), o0, o1); bits = o0; }
  else         { threefry42((u32)(j - half), (u32)j, o0, o1); bits = o1; }
#else
  threefry42((u32)(j >> 32), (u32)j, o0, o1); bits = o0 ^ o1;
#endif
  float u = __uint_as_float((bits >> 9) | 0x3f800000u) - 1.0f;
  float v = fmaxf(1e-10f, u + 1e-10f);
  return -logf(-logf(v));
}

// ---- KA: sampled stats (1/16 of row) -> threshold + exp-shift ----
__global__ void __launch_bounds__(NTA)
ka_sample(const float* __restrict__ logits, int V)
{
  const int row = blockIdx.x, tid = threadIdx.x, lane = tid & 31, wid = tid >> 5;
  if (tid == 0) g_cnt[row] = 0;
  const float4* l4 = (const float4*)(logits + (size_t)row * V);
  const int n4 = V >> 2;
  __shared__ float r0[8], r1[8], r2[8];
  __shared__ int r3[8];
  float m = __int_as_float(0xff800000), sum = 0.f, ssq = 0.f;
  int ns = 0;
  for (int i = tid; i < n4; i += NTA * 16){
    float4 v = l4[i];
    m = fmaxf(m, fmaxf(fmaxf(v.x, v.y), fmaxf(v.z, v.w)));
    sum += (v.x + v.y) + (v.z + v.w);
    ssq += v.x*v.x + v.y*v.y + v.z*v.z + v.w*v.w;
    ns += 4;
  }
  #pragma unroll
  for (int o = 16; o; o >>= 1){
    m   = fmaxf(m, __shfl_down_sync(~0u, m, o));
    sum += __shfl_down_sync(~0u, sum, o);
    ssq += __shfl_down_sync(~0u, ssq, o);
    ns  += __shfl_down_sync(~0u, ns, o);
  }
  if (lane == 0){ r0[wid] = m; r1[wid] = sum; r2[wid] = ssq; r3[wid] = ns; }
  __syncthreads();
  if (tid == 0){
    for (int w = 1; w < NTA/32; w++){
      m = fmaxf(m, r0[w]); sum += r1[w]; ssq += r2[w]; ns += r3[w];
    }
    m = r0[0] > m ? r0[0] : m; sum = sum - 0.f;   // (r0[0] already in m via w loop start)
    float mu = sum / fmaxf((float)ns, 1.f);
    float sig = sqrtf(fmaxf(ssq / fmaxf((float)ns, 1.f) - mu * mu, 0.f));
    g_T[row] = mu + 3.0f * sig;
    g_M[row] = m;
  }
}

// ---- KB: one full pass — sumexp (shift m̂) + tight-threshold gather ----
__global__ void __launch_bounds__(NTB, 6)
kb_gather(const float* __restrict__ logits, int V, int Vs)
{
  const int row = blockIdx.x / SPLITB, sl = blockIdx.x % SPLITB;
  const int tid = threadIdx.x, lane = tid & 31, wid = tid >> 5;
  const float* lrow = logits + (size_t)row * V;
  const float T = g_T[row], bm = g_M[row];
  int e0 = sl * Vs; if (e0 > V) e0 = V;
  int e1 = e0 + Vs; if (e1 > V) e1 = V;
  const int f0 = e0 >> 2, f1 = e1 >> 2;
  const float4* l4 = (const float4*)lrow;
  __shared__ float r0[NTB/32];
  float se = 0.f;
  const int iters = (f1 - f0 + NTB - 1) / NTB;
  for (int t = 0; t < iters; t++){
    int i = f0 + t * NTB + tid;
    bool in = (i < f1);
    float4 v = in ? l4[i] : make_float4(-1e30f, -1e30f, -1e30f, -1e30f);
    if (in) se += __expf(v.x-bm) + __expf(v.y-bm) + __expf(v.z-bm) + __expf(v.w-bm);
    float xs[4] = {v.x, v.y, v.z, v.w};
    u32 mk[4]; int pc[4];
    #pragma unroll
    for (int c2 = 0; c2 < 4; c2++){
      mk[c2] = __ballot_sync(~0u, in && (xs[c2] >= T));
      pc[c2] = __popc(mk[c2]);
    }
    int total = pc[0] + pc[1] + pc[2] + pc[3];
    if (total){
      int base = 0;
      if (lane == 0) base = atomicAdd(&g_cnt[row], total);
      base = __shfl_sync(~0u, base, 0);
      int run = 0, bi = i << 2;
      u32 lt = (1u << lane) - 1u;
      #pragma unroll
      for (int c2 = 0; c2 < 4; c2++){
        if (mk[c2] & (1u << lane)){
          int p = base + run + __popc(mk[c2] & lt);
          if (p < GCAP) g_cand[(size_t)row*GCAP + p] = ((u64)fkey(xs[c2]) << 32) | (u32)~(u32)(bi + c2);
        }
        run += pc[c2];
      }
    }
  }
  for (int i = (f1 << 2) + tid; i < e1; i += NTB){
    float x = lrow[i];
    se += __expf(x - bm);
    if (x >= T){
      int p = atomicAdd(&g_cnt[row], 1);
      if (p < GCAP) g_cand[(size_t)row*GCAP + p] = ((u64)fkey(x) << 32) | (u32)~(u32)i;
    }
  }
  #pragma unroll
  for (int o = 16; o; o >>= 1) se += __shfl_down_sync(~0u, se, o);
  if (lane == 0) r0[wid] = se;
  __syncthreads();
  if (tid == 0){
    for (int w = 1; w < NTB/32; w++) se += r0[w];
    g_sexp[row*SPLITB+sl] = se;
  }
}

// ---- KC: per-row finish (hash, validate, sorts, outputs) ----
__global__ void __launch_bounds__(NTC)
kc_final(const float* __restrict__ logits, const float* __restrict__ temperature,
         const float* __restrict__ presence, const float* __restrict__ frequency,
         const float* __restrict__ repetition, const float* __restrict__ top_p,
         const int* __restrict__ prompt_ids, const int* __restrict__ out_tok,
         const int* __restrict__ out_lens, const int* __restrict__ stop_ids,
         const int* __restrict__ min_toks, const int* __restrict__ top_k,
         float* __restrict__ out, int B, int V, int P, int O, int S, int MN)
{
  extern __shared__ unsigned char smraw[];
  u64* cbuf = (u64*)smraw;            // CCAP
  u32* hkey = (u32*)(cbuf + CCAP);    // HCAP
  u32* hval = hkey + HCAP;            // HCAP
  __shared__ int sh_cnt, sh_unp;
  __shared__ float e_val[TOPN], e_gum[TOPN], e_exp[TOPN];
  __shared__ u32 e_idx[TOPN];

  const int row = blockIdx.x;
  const int tid = threadIdx.x, lane = tid & 31;
  const float* lrow = logits + (size_t)row * V;

  // logZ from slice partials (shared shift m̂ -> plain sum)
  float Z = 0.f;
  #pragma unroll
  for (int s = 0; s < SPLITB; s++) Z += g_sexp[row*SPLITB+s];
  const float logZ = logf(Z);
  const float mf = g_M[row];

  int c_raw = g_cnt[row];
  int c = (c_raw < GCAP) ? c_raw : GCAP;
  for (int i = tid; i < c; i += NTC) cbuf[i] = g_cand[(size_t)row*GCAP + i];

  // penalty hash: bits[0:16) count, bit16 prompt, bit17 stop-neg
  for (int i = tid; i < HCAP; i += NTC){ hkey[i] = 0xFFFFFFFFu; hval[i] = 0u; }
  __syncthreads();
  const int olen = out_lens[row];
  const bool penal = olen < min_toks[row];
  auto insert = [&](int id, u32 orb, u32 add){
    u32 uid = (u32)id, h = ((uid * 2654435761u) >> 16) & (HCAP - 1);
    for (;;){
      u32 k = hkey[h];
      if (k == uid) break;
      if (k == 0xFFFFFFFFu){
        u32 old = atomicCAS(&hkey[h], 0xFFFFFFFFu, uid);
        if (old == 0xFFFFFFFFu || old == uid) break;
      }
      h = (h + 1) & (HCAP - 1);
    }
    if (orb) atomicOr(&hval[h], orb);
    if (add) atomicAdd(&hval[h], add);
  };
  for (int i = tid; i < P; i += NTC) insert(prompt_ids[(size_t)row*P + i], 1u<<16, 0u);
  for (int i = tid; i < O; i += NTC) if (i < olen) insert(out_tok[(size_t)row*O + i], 0u, 1u);
  if (penal) for (int i = tid; i < S; i += NTC) insert(stop_ids[(size_t)row*S + i], 1u<<17, 0u);
  __syncthreads();

  auto probe = [&](u32 idx)->u32{
    u32 h = ((idx * 2654435761u) >> 16) & (HCAP - 1);
    for (;;){
      u32 kk = hkey[h];
      if (kk == idx) return hval[h];
      if (kk == 0xFFFFFFFFu) return 0u;
      h = (h + 1) & (HCAP - 1);
    }
  };

  // validity: need total>=MN, total<=GCAP, and >=64 unpenalized candidates
  if (tid == 0){ sh_unp = 0; }
  __syncthreads();
  {
    int unp = 0;
    for (int i = tid; i < c; i += NTC){
      u32 idx = ~(u32)cbuf[i];
      if (probe(idx) == 0u) unp++;
    }
    #pragma unroll
    for (int o = 16; o; o >>= 1) unp += __shfl_down_sync(~0u, unp, o);
    if (lane == 0 && unp) atomicAdd(&sh_unp, unp);
  }
  __syncthreads();
  int needU = (64 < V) ? 64 : V;
  bool valid = (c_raw <= GCAP) && (c >= ((MN < V) ? MN : V)) && (sh_unp >= needU);

  if (!valid){
    // cold fallback: guaranteed 1348-candidate gather via float bisection
    int minc = P + O + S + TOPN; if (minc > V) minc = V;
    // crude bounds from candidates/shift
    float lo = -1e30f, hi = mf + 1.f;
    float T = g_T[row];
    for (int it = 0; it < 60; it++){
      if (tid == 0) sh_cnt = 0;
      __syncthreads();
      int cc = 0;
      for (int i = tid; i < V; i += NTC) if (lrow[i] >= T) cc++;
      #pragma unroll
      for (int o = 16; o; o >>= 1) cc += __shfl_down_sync(~0u, cc, o);
      if (lane == 0 && cc) atomicAdd(&sh_cnt, cc);
      __syncthreads();
      int tot = sh_cnt;
      if (tot >= minc && tot <= CCAP) break;
      if (tot > CCAP) lo = T; else hi = T;
      T = 0.5f * (lo + hi);
      __syncthreads();
    }
    if (tid == 0) sh_cnt = 0;
    __syncthreads();
    int vpad = V + (NTC - V % NTC) % NTC;
    for (int i = tid; i < vpad; i += NTC){
      bool pred = (i < V) && (lrow[i] >= T);
      float x = pred ? lrow[i] : 0.f;
      u32 mk = __ballot_sync(~0u, pred);
      if (mk){
        int leader = __ffs(mk) - 1, pos = 0;
        if (lane == leader) pos = atomicAdd(&sh_cnt, __popc(mk));
        pos = __shfl_sync(~0u, pos, leader);
        if (pred){
          int p = pos + __popc(mk & ((1u << lane) - 1u));
          if (p < CCAP) cbuf[p] = ((u64)fkey(x) << 32) | (u32)~(u32)i;
        }
      }
    }
    __syncthreads();
    c = sh_cnt; if (c > CCAP) c = CCAP;
  }
  if (c < 1) c = 1;

  // sort width
  int W = 256; while (W < c) W <<= 1;     // <= CCAP
  for (int i = c + tid; i < W; i += NTC) cbuf[i] = 0ULL;
  __syncthreads();
  // bitonic ascending sort of cbuf[0..W)
  for (int kk = 2; kk <= W; kk <<= 1)
    for (int j = kk >> 1; j > 0; j >>= 1){
      __syncthreads();
      for (int t = tid; t < W; t += NTC){
        int l = t ^ j;
        if (l > t){
          u64 a = cbuf[t], b2 = cbuf[l];
          bool asc = ((t & kk) == 0);
          if (asc ? (a > b2) : (a < b2)){ cbuf[t] = b2; cbuf[l] = a; }
        }
      }
    }
  __syncthreads();

  // raw top-MN outputs
  int mrounds = (MN < c) ? MN : c;
  if (tid < MN){
    if (tid < mrounds){
      u64 w = cbuf[W - 1 - tid];
      out[(size_t)B + (size_t)row*MN + tid] = (fdec((u32)(w >> 32)) - mf) - logZ;
      out[(size_t)B + (size_t)B*MN + (size_t)row*MN + tid] = (float)(~(u32)w);
    } else {
      out[(size_t)B + (size_t)row*MN + tid] = 0.f;
      out[(size_t)B + (size_t)B*MN + (size_t)row*MN + tid] = 0.f;
    }
  }
  __syncthreads();

  // transform in place: penalties + temperature
  const float rep = repetition[row], fr = frequency[row], pr = presence[row];
  const float tp = temperature[row], td = (tp < 1e-5f) ? 1.f : tp;
  for (int i = tid; i < W; i += NTC){
    u64 k = cbuf[i];
    if (k != 0ULL){
      u32 idx = ~(u32)k;
      float x = fdec((u32)(k >> 32));
      u32 info = probe(idx);
      int cv = (int)(info & 0xFFFFu);
      if (info & (1u<<17)) x = NEG_INF_F;
      if ((info & (1u<<16)) || cv > 0) x = (x > 0.f) ? (x / rep) : (x * rep);
      x = x - fr * (float)cv;
      if (cv > 0) x = x - pr;
      x = x / td;
      cbuf[i] = ((u64)fkey(x) << 32) | (u32)~idx;
    }
  }
  // sort processed keys
  for (int kk = 2; kk <= W; kk <<= 1)
    for (int j = kk >> 1; j > 0; j >>= 1){
      __syncthreads();
      for (int t = tid; t < W; t += NTC){
        int l = t ^ j;
        if (l > t){
          u64 a = cbuf[t], b2 = cbuf[l];
          bool asc = ((t & kk) == 0);
          if (asc ? (a > b2) : (a < b2)){ cbuf[t] = b2; cbuf[l] = a; }
        }
      }
    }
  __syncthreads();

  // epilogue: top-k / top-p / gumbel
  const int trounds = (TOPN < c) ? TOPN : c;
  const u64 half = ((u64)B * (u64)V) >> 1;
  if (tid < trounds){
    u64 w = cbuf[W - 1 - tid];
    float x = fdec((u32)(w >> 32));
    u32 ix = ~(u32)w;
    e_val[tid] = x; e_idx[tid] = ix;
    e_gum[tid] = gumbel_at((u64)row * (u64)V + ix, half);
  }
  __syncthreads();
  if (tid < trounds) e_exp[tid] = expf(e_val[tid] - e_val[0]);
  __syncthreads();
  if (tid == 0){
    int k = top_k[row];
    if (k < 1) k = 1;
    if (k > trounds) k = trounds;
    float kth = e_val[k - 1];
    float Ssum = 0.f; int k2 = 0;
    for (int j = 0; j < trounds; j++){
      if (e_val[j] >= kth){ Ssum += e_exp[j]; k2 = j + 1; } else break;
    }
    const float thr = top_p[row] * Ssum;
    float pref = 0.f, best = __int_as_float(0xff800000);
    u32 besti = e_idx[0];
    for (int j = 0; j < k2; j++){
      bool keep = (j == 0) || (pref < thr);
      pref += e_exp[j];
      if (keep){
        float sc = e_val[j] + e_gum[j];
        if (sc > best){ best = sc; besti = e_idx[j]; }
      }
    }
    out[row] = (float)((tp < 1e-5f) ? e_idx[0] : besti);
  }
}

extern "C" void kernel_launch(void* const* d_in, const int* in_sizes, int n_in,
                              void* d_out, int out_size)
{
  const float* logits = (const float*)d_in[0];
  int B = in_sizes[1];
  int V = in_sizes[0] / B;
  int P = in_sizes[6] / B;
  int O = in_sizes[7] / B;
  int S = in_sizes[9] / B;
  int MN = (out_size / B - 1) / 2;
  if (MN < 0) MN = 0;
  int Vs = (((V + SPLITB - 1) / SPLITB) + 31) & ~31;

  ka_sample<<<B, NTA>>>(logits, V);
  kb_gather<<<B * SPLITB, NTB>>>(logits, V, Vs);

  size_t sh = (size_t)CCAP * sizeof(u64) + (size_t)HCAP * 2 * sizeof(u32);
  cudaFuncSetAttribute(kc_final, cudaFuncAttributeMaxDynamicSharedMemorySize, (int)sh);
  kc_final<<<B, NTC, sh>>>(logits,
      (const float*)d_in[1], (const float*)d_in[2], (const float*)d_in[3],
      (const float*)d_in[4], (const float*)d_in[5],
      (const int*)d_in[6], (const int*)d_in[7], (const int*)d_in[8],
      (const int*)d_in[9], (const int*)d_in[10], (const int*)d_in[11],
      (float*)d_out, B, V, P, O, S, MN);
}